// round 11
// baseline (speedup 1.0000x reference)
#include <cuda_runtime.h>
#include <cooperative_groups.h>
namespace cg = cooperative_groups;

#define NMAX 50000
#define EMAX 800000
#define RR 3
#define HH 64
#define CC 5
#define N3MAX (NMAX * RR)
#define SLICE ((size_t)NMAX * HH)
#define CSR_BLOCKS 148
#define CSR_THREADS 1024

// ---------------- device scratch (keep total < 62 MiB) ----------------
// slices 0..2: per-relation agg means; slice 3: h1
__device__ __align__(16) float g_pool[4 * SLICE];
__device__ int   g_cnt[N3MAX];          // zero at entry (module-load zero / self-cleaned)
__device__ int   g_cur[N3MAX];
__device__ int   g_offs[N3MAX + 1];
__device__ int   g_bsum[CSR_BLOCKS];
__device__ float g_inv[N3MAX];
__device__ int   g_esrc[EMAX];
__device__ int   g_is64;

// ---------------- one cooperative kernel: detect + count + scan + fill ----------------
// grid = 148 x 1024 (1 block/SM). 151552 threads >= n3+1 = 150001.
__global__ __launch_bounds__(CSR_THREADS) void csr_k(
    const int* __restrict__ w32,
    const void* __restrict__ ei,
    const void* __restrict__ et,
    int e, int n3)
{
    cg::grid_group grid = cg::this_grid();
    __shared__ int sh[CSR_THREADS];
    __shared__ int blockPrefix;
    __shared__ int nz;

    int tid = threadIdx.x;
    int bid = blockIdx.x;
    int gthreads = gridDim.x * blockDim.x;
    int gi = bid * CSR_THREADS + tid;

    // ---- phase 0: int64/int32 width detection (block 0) ----
    if (bid == 0) {
        if (tid == 0) nz = 0;
        __syncthreads();
        int npairs = e < 1024 ? e : 1024;
        int local = 0;
        for (int j = tid; j < npairs; j += CSR_THREADS)
            if (w32[2 * j + 1] != 0) local = 1;
        if (local) atomicExch(&nz, 1);
        __syncthreads();
        if (tid == 0) g_is64 = (nz == 0) ? 1 : 0;
    }
    grid.sync();

    // hoist width flag into a register: avoids a reload per edge (alias-safe)
    const int is64 = g_is64;
    const long long* ei64 = (const long long*)ei;
    const int*       ei32 = (const int*)ei;
    const long long* et64 = (const long long*)et;
    const int*       et32 = (const int*)et;

    // ---- phase 1: degree count ----
    for (int i = gi; i < e; i += gthreads) {
        int dst = is64 ? (int)ei64[(long long)e + i] : ei32[e + i];
        int r   = is64 ? (int)et64[i]                : et32[i];
        atomicAdd(&g_cnt[dst * RR + r], 1);
    }
    grid.sync();

    // ---- phase 2: per-block scan, fused reciprocal, self-clean g_cnt ----
    int v = (gi < n3) ? g_cnt[gi] : 0;
    if (gi < n3) {
        g_inv[gi] = 1.0f / (float)(v > 0 ? v : 1);
        g_cnt[gi] = 0;                       // ready for next graph replay
    }
    sh[tid] = v;
    __syncthreads();
    for (int off = 1; off < CSR_THREADS; off <<= 1) {
        int t = (tid >= off) ? sh[tid - off] : 0;
        __syncthreads();
        sh[tid] += t;
        __syncthreads();
    }
    int incl = sh[tid];
    if (tid == CSR_THREADS - 1) g_bsum[bid] = incl;
    grid.sync();

    // ---- phase 3: prefix of block sums; write offs, seed cur ----
    if (tid < 32) {
        int run = 0;
        for (int j = tid; j < bid; j += 32) run += g_bsum[j];
        #pragma unroll
        for (int o = 16; o > 0; o >>= 1)
            run += __shfl_down_sync(0xffffffffu, run, o);
        if (tid == 0) blockPrefix = run;
    }
    __syncthreads();
    int excl = blockPrefix + incl - v;
    if (gi < n3) { g_offs[gi] = excl; g_cur[gi] = excl; }
    if (gi == n3) g_offs[n3] = e;
    grid.sync();

    // ---- phase 4: fill (g_cur pre-seeded with offsets) ----
    for (int i = gi; i < e; i += gthreads) {
        int src = is64 ? (int)ei64[i]                : ei32[i];
        int dst = is64 ? (int)ei64[(long long)e + i] : ei32[e + i];
        int r   = is64 ? (int)et64[i]                : et32[i];
        int pos = atomicAdd(&g_cur[dst * RR + r], 1);
        g_esrc[pos] = src;
    }
}

// ---------------- atomic-free aggregation: warp per (dst, rel), float2 lanes ----------------
__global__ void agg_k(const float* __restrict__ x, int n, int layer) {
    int gt = blockIdx.x * blockDim.x + threadIdx.x;
    int w = gt >> 5;
    int lane = gt & 31;
    int n3 = n * RR;
    if (w >= n3) return;

    const float2* xin = (const float2*)((layer == 1) ? x : (g_pool + 3 * SLICE));

    int s = g_offs[w], t = g_offs[w + 1];
    float2 A = make_float2(0.f, 0.f), B = A, C = A, D = A;
    int i = s;
    for (; i + 3 < t; i += 4) {
        float2 v0 = __ldg(&xin[(size_t)__ldg(&g_esrc[i])     * 32 + lane]);
        float2 v1 = __ldg(&xin[(size_t)__ldg(&g_esrc[i + 1]) * 32 + lane]);
        float2 v2 = __ldg(&xin[(size_t)__ldg(&g_esrc[i + 2]) * 32 + lane]);
        float2 v3 = __ldg(&xin[(size_t)__ldg(&g_esrc[i + 3]) * 32 + lane]);
        A.x += v0.x; A.y += v0.y;
        B.x += v1.x; B.y += v1.y;
        C.x += v2.x; C.y += v2.y;
        D.x += v3.x; D.y += v3.y;
    }
    if (i + 1 < t) {
        float2 v0 = __ldg(&xin[(size_t)__ldg(&g_esrc[i])     * 32 + lane]);
        float2 v1 = __ldg(&xin[(size_t)__ldg(&g_esrc[i + 1]) * 32 + lane]);
        A.x += v0.x; A.y += v0.y;
        B.x += v1.x; B.y += v1.y;
        i += 2;
    }
    if (i < t) {
        float2 v0 = __ldg(&xin[(size_t)__ldg(&g_esrc[i]) * 32 + lane]);
        C.x += v0.x; C.y += v0.y;
    }
    float sc = g_inv[w];
    int r = w % RR, dst = w / RR;
    float2 o;
    o.x = ((A.x + B.x) + (C.x + D.x)) * sc;
    o.y = ((A.y + B.y) + (C.y + D.y)) * sc;
    ((float2*)(g_pool + (size_t)r * SLICE + (size_t)dst * HH))[lane] = o;
}

// ---------------- packed f32x2 helpers (value semantics only) ----------------
__device__ __forceinline__ unsigned long long pack2(float x) {
    unsigned long long r;
    asm("mov.b64 %0, {%1, %1};" : "=l"(r) : "f"(x));
    return r;
}
__device__ __forceinline__ unsigned long long pack2two(float x, float y) {
    unsigned long long r;
    asm("mov.b64 %0, {%1, %2};" : "=l"(r) : "f"(x), "f"(y));
    return r;
}
__device__ __forceinline__ unsigned long long ffma2(unsigned long long a,
                                                    unsigned long long b,
                                                    unsigned long long c) {
    unsigned long long d;
    asm("fma.rn.f32x2 %0, %1, %2, %3;" : "=l"(d) : "l"(a), "l"(b), "l"(c));
    return d;
}
__device__ __forceinline__ float2 unpack2(unsigned long long v) {
    float2 f;
    asm("mov.b64 {%0, %1}, %2;" : "=f"(f.x), "=f"(f.y) : "l"(v));
    return f;
}

// ---------------- fused layer GEMM (+head on layer 2) ----------------
// 128 threads/block, one row per thread, f32x2 packed accumulators.
__global__ __launch_bounds__(128) void rgcn_gemm_k(
    const float* __restrict__ x,
    const float* __restrict__ Wrel,
    const float* __restrict__ root,
    const float* __restrict__ bias,
    const float* __restrict__ Wc,
    const float* __restrict__ bc,
    float* __restrict__ outHead,
    int n, int layer)
{
    __shared__ __align__(16) float Ws[HH * HH];
    __shared__ float Wcs[HH * CC];
    __shared__ float bcs[CC];
    int tid = threadIdx.x;
    int row = blockIdx.x * 128 + tid;
    int crow = row < n ? row : 0;

    if (layer == 2) {
        for (int i = tid; i < HH * CC; i += 128) Wcs[i] = Wc[i];
        if (tid < CC) bcs[tid] = bc[tid];
    }

    unsigned long long acc[32];
    {
        const float2* b2 = (const float2*)bias;
        #pragma unroll
        for (int j = 0; j < 32; j++) { float2 b = b2[j]; acc[j] = pack2two(b.x, b.y); }
    }

    const float* xin = (layer == 1) ? x : (g_pool + 3 * SLICE);

    for (int m = 0; m < 4; m++) {
        const float* W = (m == 0) ? root : (Wrel + (size_t)(m - 1) * HH * HH);
        __syncthreads();
        {
            const float4* w4 = (const float4*)W;
            float4* s4 = (float4*)Ws;
            for (int i = tid; i < HH * HH / 4; i += 128) s4[i] = w4[i];
        }
        __syncthreads();

        const float* in = (m == 0) ? xin : (g_pool + (size_t)(m - 1) * SLICE);
        const float4* x4 = (const float4*)(in + (size_t)crow * HH);

        #pragma unroll 4
        for (int k4 = 0; k4 < 16; k4++) {
            float4 v = x4[k4];
            #define GSTEP(E, KK)                                                   \
            {                                                                      \
                unsigned long long p = pack2(E);                                   \
                const ulonglong2* wr = (const ulonglong2*)&Ws[(4 * k4 + KK) * HH]; \
                _Pragma("unroll")                                                  \
                for (int j = 0; j < 16; j++) {                                     \
                    ulonglong2 w2 = wr[j];                                         \
                    acc[2 * j]     = ffma2(p, w2.x, acc[2 * j]);                   \
                    acc[2 * j + 1] = ffma2(p, w2.y, acc[2 * j + 1]);               \
                }                                                                  \
            }
            GSTEP(v.x, 0)
            GSTEP(v.y, 1)
            GSTEP(v.z, 2)
            GSTEP(v.w, 3)
            #undef GSTEP
        }
    }

    if (layer == 1) {
        if (row < n) {
            float4* o4 = (float4*)(g_pool + 3 * SLICE + (size_t)row * HH);
            #pragma unroll
            for (int j = 0; j < 16; j++) {
                float2 lo = unpack2(acc[2 * j]);
                float2 hi = unpack2(acc[2 * j + 1]);
                float a = lo.x > 0.f ? lo.x : 0.f;
                float b = lo.y > 0.f ? lo.y : 0.f;
                float c = hi.x > 0.f ? hi.x : 0.f;
                float d = hi.y > 0.f ? hi.y : 0.f;
                o4[j] = make_float4(a, b, c, d);
            }
        }
    } else {
        float p[CC];
        #pragma unroll
        for (int c = 0; c < CC; c++) p[c] = bcs[c];
        #pragma unroll
        for (int j = 0; j < 32; j++) {
            float2 v = unpack2(acc[j]);
            float h0 = v.x > 0.f ? v.x : 0.f;
            float h1 = v.y > 0.f ? v.y : 0.f;
            int k0 = 2 * j;
            #pragma unroll
            for (int c = 0; c < CC; c++)
                p[c] += h0 * Wcs[k0 * CC + c] + h1 * Wcs[(k0 + 1) * CC + c];
        }
        if (row < n) {
            #pragma unroll
            for (int c = 0; c < CC; c++)
                outHead[(size_t)row * CC + c] = p[c];
        }
    }
}

// ---------------- launch ----------------
extern "C" void kernel_launch(void* const* d_in, const int* in_sizes, int n_in,
                              void* d_out, int out_size)
{
    const float* x     = (const float*)d_in[0];
    const float* W1    = (const float*)d_in[1];
    const float* root1 = (const float*)d_in[2];
    const float* b1    = (const float*)d_in[3];
    const float* W2    = (const float*)d_in[4];
    const float* root2 = (const float*)d_in[5];
    const float* b2    = (const float*)d_in[6];
    const float* Wc    = (const float*)d_in[7];
    const float* bc    = (const float*)d_in[8];
    const void*  ei    = d_in[9];
    const void*  et    = d_in[10];
    float* out = (float*)d_out;

    int n  = in_sizes[0] / HH;     // 50000
    int e  = in_sizes[10];         // 800000
    int n3 = n * RR;

    // single cooperative kernel builds the whole CSR
    {
        const int* w32 = (const int*)ei;
        void* args[] = { (void*)&w32, (void*)&ei, (void*)&et, (void*)&e, (void*)&n3 };
        cudaLaunchCooperativeKernel((const void*)csr_k,
                                    dim3(CSR_BLOCKS), dim3(CSR_THREADS),
                                    args, 0, 0);
    }

    int aggBlocks  = (n3 * 32 + 255) / 256;
    int gemmBlocks = (n + 127) / 128;

    // layer 1
    agg_k<<<aggBlocks, 256>>>(x, n, 1);
    rgcn_gemm_k<<<gemmBlocks, 128>>>(x, W1, root1, b1, Wc, bc, out, n, 1);

    // layer 2 (head fused)
    agg_k<<<aggBlocks, 256>>>(x, n, 2);
    rgcn_gemm_k<<<gemmBlocks, 128>>>(x, W2, root2, b2, Wc, bc, out, n, 2);
}

// round 12
// speedup vs baseline: 1.0509x; 1.0509x over previous
#include <cuda_runtime.h>
#include <cooperative_groups.h>
namespace cg = cooperative_groups;

#define NMAX 50000
#define EMAX 800000
#define RR 3
#define HH 64
#define CC 5
#define SLICE ((size_t)NMAX * HH)
#define CSR_BLOCKS 148
#define CSR_THREADS 1024

// ---------------- device scratch (keep total < 62 MiB) ----------------
// slices 0..2: per-relation agg means; slice 3: h1
__device__ __align__(16) float g_pool[4 * SLICE];
__device__ int      g_cnt[NMAX];        // zero at entry (module-load zero / self-cleaned)
__device__ int      g_cur[NMAX];
__device__ int      g_offs[NMAX + 1];
__device__ int      g_bsum[CSR_BLOCKS];
__device__ unsigned g_edge[EMAX];       // rel<<24 | src
__device__ int      g_is64;

// ---------------- one cooperative kernel: detect + count + scan + fill ----------------
// CSR keyed by dst only; relation packed into the edge record.
__global__ __launch_bounds__(CSR_THREADS) void csr_k(
    const int* __restrict__ w32,
    const void* __restrict__ ei,
    const void* __restrict__ et,
    int e, int n)
{
    cg::grid_group grid = cg::this_grid();
    __shared__ int sh[CSR_THREADS];
    __shared__ int blockPrefix;
    __shared__ int nz;

    int tid = threadIdx.x;
    int bid = blockIdx.x;
    int gthreads = gridDim.x * blockDim.x;
    int gi = bid * CSR_THREADS + tid;

    // ---- phase 0: int64/int32 width detection (block 0) ----
    if (bid == 0) {
        if (tid == 0) nz = 0;
        __syncthreads();
        int npairs = e < 1024 ? e : 1024;
        int local = 0;
        for (int j = tid; j < npairs; j += CSR_THREADS)
            if (w32[2 * j + 1] != 0) local = 1;
        if (local) atomicExch(&nz, 1);
        __syncthreads();
        if (tid == 0) g_is64 = (nz == 0) ? 1 : 0;
    }
    grid.sync();

    // hoisted width flag (register; avoids per-edge reload across atomics)
    const int is64 = g_is64;
    const long long* ei64 = (const long long*)ei;
    const int*       ei32 = (const int*)ei;
    const long long* et64 = (const long long*)et;
    const int*       et32 = (const int*)et;

    // ---- phase 1: per-dst degree count ----
    for (int i = gi; i < e; i += gthreads) {
        int dst = is64 ? (int)ei64[(long long)e + i] : ei32[e + i];
        atomicAdd(&g_cnt[dst], 1);
    }
    grid.sync();

    // ---- phase 2: per-block scan + self-clean g_cnt ----
    int v = (gi < n) ? g_cnt[gi] : 0;
    if (gi < n) g_cnt[gi] = 0;              // ready for next graph replay
    sh[tid] = v;
    __syncthreads();
    for (int off = 1; off < CSR_THREADS; off <<= 1) {
        int t = (tid >= off) ? sh[tid - off] : 0;
        __syncthreads();
        sh[tid] += t;
        __syncthreads();
    }
    int incl = sh[tid];
    if (tid == CSR_THREADS - 1) g_bsum[bid] = incl;
    grid.sync();

    // ---- phase 3: prefix of block sums; write offs, seed cur ----
    if (tid < 32) {
        int run = 0;
        for (int j = tid; j < bid; j += 32) run += g_bsum[j];
        #pragma unroll
        for (int o = 16; o > 0; o >>= 1)
            run += __shfl_down_sync(0xffffffffu, run, o);
        if (tid == 0) blockPrefix = run;
    }
    __syncthreads();
    int excl = blockPrefix + incl - v;
    if (gi < n) { g_offs[gi] = excl; g_cur[gi] = excl; }
    if (gi == n) g_offs[n] = e;
    grid.sync();

    // ---- phase 4: fill packed edge records ----
    for (int i = gi; i < e; i += gthreads) {
        int src = is64 ? (int)ei64[i]                : ei32[i];
        int dst = is64 ? (int)ei64[(long long)e + i] : ei32[e + i];
        int r   = is64 ? (int)et64[i]                : et32[i];
        int pos = atomicAdd(&g_cur[dst], 1);
        g_edge[pos] = ((unsigned)r << 24) | (unsigned)src;
    }
}

// ---------------- node-major aggregation: warp per dst, 3 relations fused ----------------
// Per-edge: uniform rel branch; scalar-float loads (2 per row) keep MLP=8 per iteration.
#define ACCUM(RV, X0, X1)                          \
    if ((RV) == 0)      { A0 += (X0); A1 += (X1); c0++; } \
    else if ((RV) == 1) { B0 += (X0); B1 += (X1); c1++; } \
    else                { C0 += (X0); C1 += (X1); c2++; }

__global__ void agg_k(const float* __restrict__ x, int n, int layer) {
    int gt = blockIdx.x * blockDim.x + threadIdx.x;
    int w = gt >> 5;
    int lane = gt & 31;
    if (w >= n) return;

    const float* xin = (layer == 1) ? x : (g_pool + 3 * SLICE);

    int s = g_offs[w], t = g_offs[w + 1];
    float A0 = 0.f, A1 = 0.f, B0 = 0.f, B1 = 0.f, C0 = 0.f, C1 = 0.f;
    int c0 = 0, c1 = 0, c2 = 0;

    int i = s;
    for (; i + 3 < t; i += 4) {
        unsigned v0 = __ldg(&g_edge[i]);
        unsigned v1 = __ldg(&g_edge[i + 1]);
        unsigned v2 = __ldg(&g_edge[i + 2]);
        unsigned v3 = __ldg(&g_edge[i + 3]);
        const float* p0 = xin + (size_t)(v0 & 0xFFFFFFu) * HH;
        const float* p1 = xin + (size_t)(v1 & 0xFFFFFFu) * HH;
        const float* p2 = xin + (size_t)(v2 & 0xFFFFFFu) * HH;
        const float* p3 = xin + (size_t)(v3 & 0xFFFFFFu) * HH;
        float x00 = __ldg(&p0[lane]), x01 = __ldg(&p0[lane + 32]);
        float x10 = __ldg(&p1[lane]), x11 = __ldg(&p1[lane + 32]);
        float x20 = __ldg(&p2[lane]), x21 = __ldg(&p2[lane + 32]);
        float x30 = __ldg(&p3[lane]), x31 = __ldg(&p3[lane + 32]);
        int r0 = v0 >> 24, r1 = v1 >> 24, r2 = v2 >> 24, r3 = v3 >> 24;
        ACCUM(r0, x00, x01)
        ACCUM(r1, x10, x11)
        ACCUM(r2, x20, x21)
        ACCUM(r3, x30, x31)
    }
    for (; i < t; i++) {
        unsigned v0 = __ldg(&g_edge[i]);
        const float* p0 = xin + (size_t)(v0 & 0xFFFFFFu) * HH;
        float x00 = __ldg(&p0[lane]), x01 = __ldg(&p0[lane + 32]);
        int r0 = v0 >> 24;
        ACCUM(r0, x00, x01)
    }

    float i0 = 1.0f / (float)(c0 > 0 ? c0 : 1);
    float i1 = 1.0f / (float)(c1 > 0 ? c1 : 1);
    float i2 = 1.0f / (float)(c2 > 0 ? c2 : 1);

    float* o0 = g_pool + 0 * SLICE + (size_t)w * HH;
    float* o1 = g_pool + 1 * SLICE + (size_t)w * HH;
    float* o2 = g_pool + 2 * SLICE + (size_t)w * HH;
    o0[lane] = A0 * i0; o0[lane + 32] = A1 * i0;
    o1[lane] = B0 * i1; o1[lane + 32] = B1 * i1;
    o2[lane] = C0 * i2; o2[lane + 32] = C1 * i2;
}
#undef ACCUM

// ---------------- packed f32x2 helpers (value semantics only) ----------------
__device__ __forceinline__ unsigned long long pack2(float x) {
    unsigned long long r;
    asm("mov.b64 %0, {%1, %1};" : "=l"(r) : "f"(x));
    return r;
}
__device__ __forceinline__ unsigned long long pack2two(float x, float y) {
    unsigned long long r;
    asm("mov.b64 %0, {%1, %2};" : "=l"(r) : "f"(x), "f"(y));
    return r;
}
__device__ __forceinline__ unsigned long long ffma2(unsigned long long a,
                                                    unsigned long long b,
                                                    unsigned long long c) {
    unsigned long long d;
    asm("fma.rn.f32x2 %0, %1, %2, %3;" : "=l"(d) : "l"(a), "l"(b), "l"(c));
    return d;
}
__device__ __forceinline__ float2 unpack2(unsigned long long v) {
    float2 f;
    asm("mov.b64 {%0, %1}, %2;" : "=f"(f.x), "=f"(f.y) : "l"(v));
    return f;
}

// ---------------- fused layer GEMM (+head on layer 2) ----------------
// 128 threads/block, one row per thread, f32x2 packed accumulators.
__global__ __launch_bounds__(128) void rgcn_gemm_k(
    const float* __restrict__ x,
    const float* __restrict__ Wrel,
    const float* __restrict__ root,
    const float* __restrict__ bias,
    const float* __restrict__ Wc,
    const float* __restrict__ bc,
    float* __restrict__ outHead,
    int n, int layer)
{
    __shared__ __align__(16) float Ws[HH * HH];
    __shared__ float Wcs[HH * CC];
    __shared__ float bcs[CC];
    int tid = threadIdx.x;
    int row = blockIdx.x * 128 + tid;
    int crow = row < n ? row : 0;

    if (layer == 2) {
        for (int i = tid; i < HH * CC; i += 128) Wcs[i] = Wc[i];
        if (tid < CC) bcs[tid] = bc[tid];
    }

    unsigned long long acc[32];
    {
        const float2* b2 = (const float2*)bias;
        #pragma unroll
        for (int j = 0; j < 32; j++) { float2 b = b2[j]; acc[j] = pack2two(b.x, b.y); }
    }

    const float* xin = (layer == 1) ? x : (g_pool + 3 * SLICE);

    for (int m = 0; m < 4; m++) {
        const float* W = (m == 0) ? root : (Wrel + (size_t)(m - 1) * HH * HH);
        __syncthreads();
        {
            const float4* w4 = (const float4*)W;
            float4* s4 = (float4*)Ws;
            for (int i = tid; i < HH * HH / 4; i += 128) s4[i] = w4[i];
        }
        __syncthreads();

        const float* in = (m == 0) ? xin : (g_pool + (size_t)(m - 1) * SLICE);
        const float4* x4 = (const float4*)(in + (size_t)crow * HH);

        #pragma unroll 4
        for (int k4 = 0; k4 < 16; k4++) {
            float4 v = x4[k4];
            #define GSTEP(E, KK)                                                   \
            {                                                                      \
                unsigned long long p = pack2(E);                                   \
                const ulonglong2* wr = (const ulonglong2*)&Ws[(4 * k4 + KK) * HH]; \
                _Pragma("unroll")                                                  \
                for (int j = 0; j < 16; j++) {                                     \
                    ulonglong2 w2 = wr[j];                                         \
                    acc[2 * j]     = ffma2(p, w2.x, acc[2 * j]);                   \
                    acc[2 * j + 1] = ffma2(p, w2.y, acc[2 * j + 1]);               \
                }                                                                  \
            }
            GSTEP(v.x, 0)
            GSTEP(v.y, 1)
            GSTEP(v.z, 2)
            GSTEP(v.w, 3)
            #undef GSTEP
        }
    }

    if (layer == 1) {
        if (row < n) {
            float4* o4 = (float4*)(g_pool + 3 * SLICE + (size_t)row * HH);
            #pragma unroll
            for (int j = 0; j < 16; j++) {
                float2 lo = unpack2(acc[2 * j]);
                float2 hi = unpack2(acc[2 * j + 1]);
                float a = lo.x > 0.f ? lo.x : 0.f;
                float b = lo.y > 0.f ? lo.y : 0.f;
                float c = hi.x > 0.f ? hi.x : 0.f;
                float d = hi.y > 0.f ? hi.y : 0.f;
                o4[j] = make_float4(a, b, c, d);
            }
        }
    } else {
        float p[CC];
        #pragma unroll
        for (int c = 0; c < CC; c++) p[c] = bcs[c];
        #pragma unroll
        for (int j = 0; j < 32; j++) {
            float2 v = unpack2(acc[j]);
            float h0 = v.x > 0.f ? v.x : 0.f;
            float h1 = v.y > 0.f ? v.y : 0.f;
            int k0 = 2 * j;
            #pragma unroll
            for (int c = 0; c < CC; c++)
                p[c] += h0 * Wcs[k0 * CC + c] + h1 * Wcs[(k0 + 1) * CC + c];
        }
        if (row < n) {
            #pragma unroll
            for (int c = 0; c < CC; c++)
                outHead[(size_t)row * CC + c] = p[c];
        }
    }
}

// ---------------- launch ----------------
extern "C" void kernel_launch(void* const* d_in, const int* in_sizes, int n_in,
                              void* d_out, int out_size)
{
    const float* x     = (const float*)d_in[0];
    const float* W1    = (const float*)d_in[1];
    const float* root1 = (const float*)d_in[2];
    const float* b1    = (const float*)d_in[3];
    const float* W2    = (const float*)d_in[4];
    const float* root2 = (const float*)d_in[5];
    const float* b2    = (const float*)d_in[6];
    const float* Wc    = (const float*)d_in[7];
    const float* bc    = (const float*)d_in[8];
    const void*  ei    = d_in[9];
    const void*  et    = d_in[10];
    float* out = (float*)d_out;

    int n  = in_sizes[0] / HH;     // 50000
    int e  = in_sizes[10];         // 800000

    // single cooperative kernel builds the dst-keyed CSR
    {
        const int* w32 = (const int*)ei;
        void* args[] = { (void*)&w32, (void*)&ei, (void*)&et, (void*)&e, (void*)&n };
        cudaLaunchCooperativeKernel((const void*)csr_k,
                                    dim3(CSR_BLOCKS), dim3(CSR_THREADS),
                                    args, 0, 0);
    }

    int aggBlocks  = (n * 32 + 255) / 256;
    int gemmBlocks = (n + 127) / 128;

    // layer 1
    agg_k<<<aggBlocks, 256>>>(x, n, 1);
    rgcn_gemm_k<<<gemmBlocks, 128>>>(x, W1, root1, b1, Wc, bc, out, n, 1);

    // layer 2 (head fused)
    agg_k<<<aggBlocks, 256>>>(x, n, 2);
    rgcn_gemm_k<<<gemmBlocks, 128>>>(x, W2, root2, b2, Wc, bc, out, n, 2);
}

// round 13
// speedup vs baseline: 1.0984x; 1.0452x over previous
#include <cuda_runtime.h>
#include <cooperative_groups.h>
namespace cg = cooperative_groups;

#define NMAX 50000
#define EMAX 800000
#define RR 3
#define HH 64
#define CC 5
#define N3MAX (NMAX * RR)
#define SLICE ((size_t)NMAX * HH)
#define CSR_BLOCKS 148
#define CSR_THREADS 1024

// ---------------- device scratch (keep total < 62 MiB) ----------------
// slices 0..2: per-relation agg means; slice 3: h1
__device__ __align__(16) float g_pool[4 * SLICE];
__device__ int   g_cnt[N3MAX];          // zero at entry (module-load zero / self-cleaned)
__device__ int   g_cur[N3MAX];
__device__ int   g_offs[N3MAX + 1];
__device__ int   g_bsum[CSR_BLOCKS];
__device__ int   g_esrc[EMAX];
__device__ int   g_is64;

// ---------------- one cooperative kernel: detect + count + scan + fill ----------------
// CSR keyed by dst*3+r  ->  low atomic contention AND per-dst-contiguous segments.
__global__ __launch_bounds__(CSR_THREADS) void csr_k(
    const int* __restrict__ w32,
    const void* __restrict__ ei,
    const void* __restrict__ et,
    int e, int n3)
{
    cg::grid_group grid = cg::this_grid();
    __shared__ int sh[CSR_THREADS];
    __shared__ int blockPrefix;
    __shared__ int nz;

    int tid = threadIdx.x;
    int bid = blockIdx.x;
    int gthreads = gridDim.x * blockDim.x;
    int gi = bid * CSR_THREADS + tid;

    // ---- phase 0: int64/int32 width detection (block 0) ----
    if (bid == 0) {
        if (tid == 0) nz = 0;
        __syncthreads();
        int npairs = e < 1024 ? e : 1024;
        int local = 0;
        for (int j = tid; j < npairs; j += CSR_THREADS)
            if (w32[2 * j + 1] != 0) local = 1;
        if (local) atomicExch(&nz, 1);
        __syncthreads();
        if (tid == 0) g_is64 = (nz == 0) ? 1 : 0;
    }
    grid.sync();

    // hoisted width flag (register; avoids per-edge reload across atomics)
    const int is64 = g_is64;
    const long long* ei64 = (const long long*)ei;
    const int*       ei32 = (const int*)ei;
    const long long* et64 = (const long long*)et;
    const int*       et32 = (const int*)et;

    // ---- phase 1: degree count per (dst, rel) ----
    for (int i = gi; i < e; i += gthreads) {
        int dst = is64 ? (int)ei64[(long long)e + i] : ei32[e + i];
        int r   = is64 ? (int)et64[i]                : et32[i];
        atomicAdd(&g_cnt[dst * RR + r], 1);
    }
    grid.sync();

    // ---- phase 2: per-block scan + self-clean g_cnt ----
    int v = (gi < n3) ? g_cnt[gi] : 0;
    if (gi < n3) g_cnt[gi] = 0;             // ready for next graph replay
    sh[tid] = v;
    __syncthreads();
    for (int off = 1; off < CSR_THREADS; off <<= 1) {
        int t = (tid >= off) ? sh[tid - off] : 0;
        __syncthreads();
        sh[tid] += t;
        __syncthreads();
    }
    int incl = sh[tid];
    if (tid == CSR_THREADS - 1) g_bsum[bid] = incl;
    grid.sync();

    // ---- phase 3: prefix of block sums; write offs, seed cur ----
    if (tid < 32) {
        int run = 0;
        for (int j = tid; j < bid; j += 32) run += g_bsum[j];
        #pragma unroll
        for (int o = 16; o > 0; o >>= 1)
            run += __shfl_down_sync(0xffffffffu, run, o);
        if (tid == 0) blockPrefix = run;
    }
    __syncthreads();
    int excl = blockPrefix + incl - v;
    if (gi < n3) { g_offs[gi] = excl; g_cur[gi] = excl; }
    if (gi == n3) g_offs[n3] = e;
    grid.sync();

    // ---- phase 4: fill source indices ----
    for (int i = gi; i < e; i += gthreads) {
        int src = is64 ? (int)ei64[i]                : ei32[i];
        int dst = is64 ? (int)ei64[(long long)e + i] : ei32[e + i];
        int r   = is64 ? (int)et64[i]                : et32[i];
        int pos = atomicAdd(&g_cur[dst * RR + r], 1);
        g_esrc[pos] = src;
    }
}

// ---------------- node-major aggregation: warp per dst, relation subranges ----------------
// Segments for one dst are contiguous: [offs[3w+r], offs[3w+r+1]) for r=0..2.
// No per-edge relation decode or predication; counts come from offset diffs.
__global__ void agg_k(const float* __restrict__ x, int n, int layer) {
    int gt = blockIdx.x * blockDim.x + threadIdx.x;
    int w = gt >> 5;
    int lane = gt & 31;
    if (w >= n) return;

    const float* xin = (layer == 1) ? x : (g_pool + 3 * SLICE);

    int o0 = __ldg(&g_offs[3 * w]);
    int o1 = __ldg(&g_offs[3 * w + 1]);
    int o2 = __ldg(&g_offs[3 * w + 2]);
    int o3 = __ldg(&g_offs[3 * w + 3]);

    #pragma unroll
    for (int r = 0; r < RR; r++) {
        int s = (r == 0) ? o0 : (r == 1) ? o1 : o2;
        int t = (r == 0) ? o1 : (r == 1) ? o2 : o3;

        float A0 = 0.f, A1 = 0.f, B0 = 0.f, B1 = 0.f;
        float C0 = 0.f, C1 = 0.f, D0 = 0.f, D1 = 0.f;
        int i = s;
        for (; i + 3 < t; i += 4) {
            const float* p0 = xin + (size_t)__ldg(&g_esrc[i])     * HH;
            const float* p1 = xin + (size_t)__ldg(&g_esrc[i + 1]) * HH;
            const float* p2 = xin + (size_t)__ldg(&g_esrc[i + 2]) * HH;
            const float* p3 = xin + (size_t)__ldg(&g_esrc[i + 3]) * HH;
            A0 += __ldg(&p0[lane]); A1 += __ldg(&p0[lane + 32]);
            B0 += __ldg(&p1[lane]); B1 += __ldg(&p1[lane + 32]);
            C0 += __ldg(&p2[lane]); C1 += __ldg(&p2[lane + 32]);
            D0 += __ldg(&p3[lane]); D1 += __ldg(&p3[lane + 32]);
        }
        if (i + 1 < t) {
            const float* p0 = xin + (size_t)__ldg(&g_esrc[i])     * HH;
            const float* p1 = xin + (size_t)__ldg(&g_esrc[i + 1]) * HH;
            A0 += __ldg(&p0[lane]); A1 += __ldg(&p0[lane + 32]);
            B0 += __ldg(&p1[lane]); B1 += __ldg(&p1[lane + 32]);
            i += 2;
        }
        if (i < t) {
            const float* p0 = xin + (size_t)__ldg(&g_esrc[i]) * HH;
            C0 += __ldg(&p0[lane]); C1 += __ldg(&p0[lane + 32]);
        }

        int cnt = t - s;
        float inv = 1.0f / (float)(cnt > 0 ? cnt : 1);
        float* o = g_pool + (size_t)r * SLICE + (size_t)w * HH;
        o[lane]      = ((A0 + B0) + (C0 + D0)) * inv;
        o[lane + 32] = ((A1 + B1) + (C1 + D1)) * inv;
    }
}

// ---------------- packed f32x2 helpers (value semantics only) ----------------
__device__ __forceinline__ unsigned long long pack2(float x) {
    unsigned long long r;
    asm("mov.b64 %0, {%1, %1};" : "=l"(r) : "f"(x));
    return r;
}
__device__ __forceinline__ unsigned long long pack2two(float x, float y) {
    unsigned long long r;
    asm("mov.b64 %0, {%1, %2};" : "=l"(r) : "f"(x), "f"(y));
    return r;
}
__device__ __forceinline__ unsigned long long ffma2(unsigned long long a,
                                                    unsigned long long b,
                                                    unsigned long long c) {
    unsigned long long d;
    asm("fma.rn.f32x2 %0, %1, %2, %3;" : "=l"(d) : "l"(a), "l"(b), "l"(c));
    return d;
}
__device__ __forceinline__ float2 unpack2(unsigned long long v) {
    float2 f;
    asm("mov.b64 {%0, %1}, %2;" : "=f"(f.x), "=f"(f.y) : "l"(v));
    return f;
}

// ---------------- fused layer GEMM (+head on layer 2) ----------------
// 128 threads/block, one row per thread, f32x2 packed accumulators.
__global__ __launch_bounds__(128) void rgcn_gemm_k(
    const float* __restrict__ x,
    const float* __restrict__ Wrel,
    const float* __restrict__ root,
    const float* __restrict__ bias,
    const float* __restrict__ Wc,
    const float* __restrict__ bc,
    float* __restrict__ outHead,
    int n, int layer)
{
    __shared__ __align__(16) float Ws[HH * HH];
    __shared__ float Wcs[HH * CC];
    __shared__ float bcs[CC];
    int tid = threadIdx.x;
    int row = blockIdx.x * 128 + tid;
    int crow = row < n ? row : 0;

    if (layer == 2) {
        for (int i = tid; i < HH * CC; i += 128) Wcs[i] = Wc[i];
        if (tid < CC) bcs[tid] = bc[tid];
    }

    unsigned long long acc[32];
    {
        const float2* b2 = (const float2*)bias;
        #pragma unroll
        for (int j = 0; j < 32; j++) { float2 b = b2[j]; acc[j] = pack2two(b.x, b.y); }
    }

    const float* xin = (layer == 1) ? x : (g_pool + 3 * SLICE);

    for (int m = 0; m < 4; m++) {
        const float* W = (m == 0) ? root : (Wrel + (size_t)(m - 1) * HH * HH);
        __syncthreads();
        {
            const float4* w4 = (const float4*)W;
            float4* s4 = (float4*)Ws;
            for (int i = tid; i < HH * HH / 4; i += 128) s4[i] = w4[i];
        }
        __syncthreads();

        const float* in = (m == 0) ? xin : (g_pool + (size_t)(m - 1) * SLICE);
        const float4* x4 = (const float4*)(in + (size_t)crow * HH);

        #pragma unroll 4
        for (int k4 = 0; k4 < 16; k4++) {
            float4 v = x4[k4];
            #define GSTEP(E, KK)                                                   \
            {                                                                      \
                unsigned long long p = pack2(E);                                   \
                const ulonglong2* wr = (const ulonglong2*)&Ws[(4 * k4 + KK) * HH]; \
                _Pragma("unroll")                                                  \
                for (int j = 0; j < 16; j++) {                                     \
                    ulonglong2 w2 = wr[j];                                         \
                    acc[2 * j]     = ffma2(p, w2.x, acc[2 * j]);                   \
                    acc[2 * j + 1] = ffma2(p, w2.y, acc[2 * j + 1]);               \
                }                                                                  \
            }
            GSTEP(v.x, 0)
            GSTEP(v.y, 1)
            GSTEP(v.z, 2)
            GSTEP(v.w, 3)
            #undef GSTEP
        }
    }

    if (layer == 1) {
        if (row < n) {
            float4* o4 = (float4*)(g_pool + 3 * SLICE + (size_t)row * HH);
            #pragma unroll
            for (int j = 0; j < 16; j++) {
                float2 lo = unpack2(acc[2 * j]);
                float2 hi = unpack2(acc[2 * j + 1]);
                float a = lo.x > 0.f ? lo.x : 0.f;
                float b = lo.y > 0.f ? lo.y : 0.f;
                float c = hi.x > 0.f ? hi.x : 0.f;
                float d = hi.y > 0.f ? hi.y : 0.f;
                o4[j] = make_float4(a, b, c, d);
            }
        }
    } else {
        float p[CC];
        #pragma unroll
        for (int c = 0; c < CC; c++) p[c] = bcs[c];
        #pragma unroll
        for (int j = 0; j < 32; j++) {
            float2 v = unpack2(acc[j]);
            float h0 = v.x > 0.f ? v.x : 0.f;
            float h1 = v.y > 0.f ? v.y : 0.f;
            int k0 = 2 * j;
            #pragma unroll
            for (int c = 0; c < CC; c++)
                p[c] += h0 * Wcs[k0 * CC + c] + h1 * Wcs[(k0 + 1) * CC + c];
        }
        if (row < n) {
            #pragma unroll
            for (int c = 0; c < CC; c++)
                outHead[(size_t)row * CC + c] = p[c];
        }
    }
}

// ---------------- launch ----------------
extern "C" void kernel_launch(void* const* d_in, const int* in_sizes, int n_in,
                              void* d_out, int out_size)
{
    const float* x     = (const float*)d_in[0];
    const float* W1    = (const float*)d_in[1];
    const float* root1 = (const float*)d_in[2];
    const float* b1    = (const float*)d_in[3];
    const float* W2    = (const float*)d_in[4];
    const float* root2 = (const float*)d_in[5];
    const float* b2    = (const float*)d_in[6];
    const float* Wc    = (const float*)d_in[7];
    const float* bc    = (const float*)d_in[8];
    const void*  ei    = d_in[9];
    const void*  et    = d_in[10];
    float* out = (float*)d_out;

    int n  = in_sizes[0] / HH;     // 50000
    int e  = in_sizes[10];         // 800000
    int n3 = n * RR;

    // single cooperative kernel builds the (dst,rel)-keyed CSR
    {
        const int* w32 = (const int*)ei;
        void* args[] = { (void*)&w32, (void*)&ei, (void*)&et, (void*)&e, (void*)&n3 };
        cudaLaunchCooperativeKernel((const void*)csr_k,
                                    dim3(CSR_BLOCKS), dim3(CSR_THREADS),
                                    args, 0, 0);
    }

    int aggBlocks  = (n * 32 + 255) / 256;
    int gemmBlocks = (n + 127) / 128;

    // layer 1
    agg_k<<<aggBlocks, 256>>>(x, n, 1);
    rgcn_gemm_k<<<gemmBlocks, 128>>>(x, W1, root1, b1, Wc, bc, out, n, 1);

    // layer 2 (head fused)
    agg_k<<<aggBlocks, 256>>>(x, n, 2);
    rgcn_gemm_k<<<gemmBlocks, 128>>>(x, W2, root2, b2, Wc, bc, out, n, 2);
}

// round 14
// speedup vs baseline: 1.1054x; 1.0065x over previous
#include <cuda_runtime.h>
#include <cooperative_groups.h>
namespace cg = cooperative_groups;

#define NMAX 50000
#define EMAX 800000
#define RR 3
#define HH 64
#define CC 5
#define N3MAX (NMAX * RR)
#define SLICE ((size_t)NMAX * HH)
#define CSR_BLOCKS 148
#define CSR_THREADS 1024

typedef unsigned long long u64;

// ---------------- device scratch (total ~59.1 MiB < 62 MiB proven limit) ----------------
// slices 0..2: per-relation agg means; slice 3: h1
__device__ __align__(16) float g_pool[4 * SLICE];
__device__ int  g_cnt[N3MAX];           // zero at entry (module-load zero / self-cleaned)
__device__ int  g_offs[N3MAX + 1];
__device__ int  g_bsum[CSR_BLOCKS];
__device__ u64  g_krec[EMAX];           // key(18b) | rank(28b) | src(18b)
__device__ int  g_esrc[EMAX];

// ---------------- one cooperative kernel: detect + count&rank + scan + place ----------------
// Single atomic pass: the count atomicAdd returns each edge's rank; fill is atomic-free.
__global__ __launch_bounds__(CSR_THREADS) void csr_k(
    const int* __restrict__ w32,
    const void* __restrict__ ei,
    const void* __restrict__ et,
    int e, int n3)
{
    cg::grid_group grid = cg::this_grid();
    __shared__ int sh[CSR_THREADS];
    __shared__ int blockPrefix;
    __shared__ int nz;

    int tid = threadIdx.x;
    int bid = blockIdx.x;
    int gthreads = gridDim.x * blockDim.x;
    int gi = bid * CSR_THREADS + tid;

    // ---- phase 0: per-block int64/int32 width detection (no grid.sync needed) ----
    if (tid == 0) nz = 0;
    __syncthreads();
    {
        int npairs = e < 1024 ? e : 1024;
        int local = 0;
        for (int j = tid; j < npairs; j += CSR_THREADS)
            if (w32[2 * j + 1] != 0) local = 1;
        if (local) atomicExch(&nz, 1);
    }
    __syncthreads();
    const int is64 = (nz == 0);

    const long long* ei64 = (const long long*)ei;
    const int*       ei32 = (const int*)ei;
    const long long* et64 = (const long long*)et;
    const int*       et32 = (const int*)et;

    // ---- phase 1: single edge-decode pass — count + rank + packed record ----
    for (int i = gi; i < e; i += gthreads) {
        int src = is64 ? (int)ei64[i]                : ei32[i];
        int dst = is64 ? (int)ei64[(long long)e + i] : ei32[e + i];
        int r   = is64 ? (int)et64[i]                : et32[i];
        int key = dst * RR + r;
        int rank = atomicAdd(&g_cnt[key], 1);
        g_krec[i] = ((u64)key << 46) | ((u64)rank << 18) | (u64)(unsigned)src;
    }
    grid.sync();

    // ---- phase 2: per-block scan + self-clean g_cnt ----
    int v = (gi < n3) ? g_cnt[gi] : 0;
    if (gi < n3) g_cnt[gi] = 0;             // ready for next graph replay
    sh[tid] = v;
    __syncthreads();
    for (int off = 1; off < CSR_THREADS; off <<= 1) {
        int t = (tid >= off) ? sh[tid - off] : 0;
        __syncthreads();
        sh[tid] += t;
        __syncthreads();
    }
    int incl = sh[tid];
    if (tid == CSR_THREADS - 1) g_bsum[bid] = incl;
    grid.sync();

    // ---- phase 3: prefix of block sums; write offs ----
    if (tid < 32) {
        int run = 0;
        for (int j = tid; j < bid; j += 32) run += g_bsum[j];
        #pragma unroll
        for (int o = 16; o > 0; o >>= 1)
            run += __shfl_down_sync(0xffffffffu, run, o);
        if (tid == 0) blockPrefix = run;
    }
    __syncthreads();
    if (gi < n3) g_offs[gi] = blockPrefix + incl - v;
    if (gi == n3) g_offs[n3] = e;
    grid.sync();

    // ---- phase 4: atomic-free placement from packed records ----
    for (int i = gi; i < e; i += gthreads) {
        u64 rec = g_krec[i];
        int key  = (int)(rec >> 46);
        int rank = (int)((rec >> 18) & 0xFFFFFFFu);
        int src  = (int)(rec & 0x3FFFFu);
        g_esrc[g_offs[key] + rank] = src;
    }
}

// ---------------- node-major aggregation: warp per dst, relation subranges ----------------
__global__ void agg_k(const float* __restrict__ x, int n, int layer) {
    int gt = blockIdx.x * blockDim.x + threadIdx.x;
    int w = gt >> 5;
    int lane = gt & 31;
    if (w >= n) return;

    const float* xin = (layer == 1) ? x : (g_pool + 3 * SLICE);

    int o0 = __ldg(&g_offs[3 * w]);
    int o1 = __ldg(&g_offs[3 * w + 1]);
    int o2 = __ldg(&g_offs[3 * w + 2]);
    int o3 = __ldg(&g_offs[3 * w + 3]);

    #pragma unroll
    for (int r = 0; r < RR; r++) {
        int s = (r == 0) ? o0 : (r == 1) ? o1 : o2;
        int t = (r == 0) ? o1 : (r == 1) ? o2 : o3;

        float A0 = 0.f, A1 = 0.f, B0 = 0.f, B1 = 0.f;
        float C0 = 0.f, C1 = 0.f, D0 = 0.f, D1 = 0.f;
        int i = s;
        for (; i + 3 < t; i += 4) {
            const float* p0 = xin + (size_t)__ldg(&g_esrc[i])     * HH;
            const float* p1 = xin + (size_t)__ldg(&g_esrc[i + 1]) * HH;
            const float* p2 = xin + (size_t)__ldg(&g_esrc[i + 2]) * HH;
            const float* p3 = xin + (size_t)__ldg(&g_esrc[i + 3]) * HH;
            A0 += __ldg(&p0[lane]); A1 += __ldg(&p0[lane + 32]);
            B0 += __ldg(&p1[lane]); B1 += __ldg(&p1[lane + 32]);
            C0 += __ldg(&p2[lane]); C1 += __ldg(&p2[lane + 32]);
            D0 += __ldg(&p3[lane]); D1 += __ldg(&p3[lane + 32]);
        }
        if (i + 1 < t) {
            const float* p0 = xin + (size_t)__ldg(&g_esrc[i])     * HH;
            const float* p1 = xin + (size_t)__ldg(&g_esrc[i + 1]) * HH;
            A0 += __ldg(&p0[lane]); A1 += __ldg(&p0[lane + 32]);
            B0 += __ldg(&p1[lane]); B1 += __ldg(&p1[lane + 32]);
            i += 2;
        }
        if (i < t) {
            const float* p0 = xin + (size_t)__ldg(&g_esrc[i]) * HH;
            C0 += __ldg(&p0[lane]); C1 += __ldg(&p0[lane + 32]);
        }

        int cnt = t - s;
        float inv = 1.0f / (float)(cnt > 0 ? cnt : 1);
        float* o = g_pool + (size_t)r * SLICE + (size_t)w * HH;
        o[lane]      = ((A0 + B0) + (C0 + D0)) * inv;
        o[lane + 32] = ((A1 + B1) + (C1 + D1)) * inv;
    }
}

// ---------------- packed f32x2 helpers (value semantics only) ----------------
__device__ __forceinline__ u64 pack2(float x) {
    u64 r;
    asm("mov.b64 %0, {%1, %1};" : "=l"(r) : "f"(x));
    return r;
}
__device__ __forceinline__ u64 pack2two(float x, float y) {
    u64 r;
    asm("mov.b64 %0, {%1, %2};" : "=l"(r) : "f"(x), "f"(y));
    return r;
}
__device__ __forceinline__ u64 ffma2(u64 a, u64 b, u64 c) {
    u64 d;
    asm("fma.rn.f32x2 %0, %1, %2, %3;" : "=l"(d) : "l"(a), "l"(b), "l"(c));
    return d;
}
__device__ __forceinline__ float2 unpack2(u64 v) {
    float2 f;
    asm("mov.b64 {%0, %1}, %2;" : "=f"(f.x), "=f"(f.y) : "l"(v));
    return f;
}

// ---------------- fused layer GEMM (+head on layer 2) ----------------
// 128 threads/block, one row per thread, f32x2 packed accumulators.
__global__ __launch_bounds__(128) void rgcn_gemm_k(
    const float* __restrict__ x,
    const float* __restrict__ Wrel,
    const float* __restrict__ root,
    const float* __restrict__ bias,
    const float* __restrict__ Wc,
    const float* __restrict__ bc,
    float* __restrict__ outHead,
    int n, int layer)
{
    __shared__ __align__(16) float Ws[HH * HH];
    __shared__ float Wcs[HH * CC];
    __shared__ float bcs[CC];
    int tid = threadIdx.x;
    int row = blockIdx.x * 128 + tid;
    int crow = row < n ? row : 0;

    if (layer == 2) {
        for (int i = tid; i < HH * CC; i += 128) Wcs[i] = Wc[i];
        if (tid < CC) bcs[tid] = bc[tid];
    }

    u64 acc[32];
    {
        const float2* b2 = (const float2*)bias;
        #pragma unroll
        for (int j = 0; j < 32; j++) { float2 b = b2[j]; acc[j] = pack2two(b.x, b.y); }
    }

    const float* xin = (layer == 1) ? x : (g_pool + 3 * SLICE);

    for (int m = 0; m < 4; m++) {
        const float* W = (m == 0) ? root : (Wrel + (size_t)(m - 1) * HH * HH);
        __syncthreads();
        {
            const float4* w4 = (const float4*)W;
            float4* s4 = (float4*)Ws;
            for (int i = tid; i < HH * HH / 4; i += 128) s4[i] = w4[i];
        }
        __syncthreads();

        const float* in = (m == 0) ? xin : (g_pool + (size_t)(m - 1) * SLICE);
        const float4* x4 = (const float4*)(in + (size_t)crow * HH);

        #pragma unroll 4
        for (int k4 = 0; k4 < 16; k4++) {
            float4 v = x4[k4];
            #define GSTEP(E, KK)                                                   \
            {                                                                      \
                u64 p = pack2(E);                                                  \
                const ulonglong2* wr = (const ulonglong2*)&Ws[(4 * k4 + KK) * HH]; \
                _Pragma("unroll")                                                  \
                for (int j = 0; j < 16; j++) {                                     \
                    ulonglong2 w2 = wr[j];                                         \
                    acc[2 * j]     = ffma2(p, w2.x, acc[2 * j]);                   \
                    acc[2 * j + 1] = ffma2(p, w2.y, acc[2 * j + 1]);               \
                }                                                                  \
            }
            GSTEP(v.x, 0)
            GSTEP(v.y, 1)
            GSTEP(v.z, 2)
            GSTEP(v.w, 3)
            #undef GSTEP
        }
    }

    if (layer == 1) {
        if (row < n) {
            float4* o4 = (float4*)(g_pool + 3 * SLICE + (size_t)row * HH);
            #pragma unroll
            for (int j = 0; j < 16; j++) {
                float2 lo = unpack2(acc[2 * j]);
                float2 hi = unpack2(acc[2 * j + 1]);
                float a = lo.x > 0.f ? lo.x : 0.f;
                float b = lo.y > 0.f ? lo.y : 0.f;
                float c = hi.x > 0.f ? hi.x : 0.f;
                float d = hi.y > 0.f ? hi.y : 0.f;
                o4[j] = make_float4(a, b, c, d);
            }
        }
    } else {
        float p[CC];
        #pragma unroll
        for (int c = 0; c < CC; c++) p[c] = bcs[c];
        #pragma unroll
        for (int j = 0; j < 32; j++) {
            float2 v = unpack2(acc[j]);
            float h0 = v.x > 0.f ? v.x : 0.f;
            float h1 = v.y > 0.f ? v.y : 0.f;
            int k0 = 2 * j;
            #pragma unroll
            for (int c = 0; c < CC; c++)
                p[c] += h0 * Wcs[k0 * CC + c] + h1 * Wcs[(k0 + 1) * CC + c];
        }
        if (row < n) {
            #pragma unroll
            for (int c = 0; c < CC; c++)
                outHead[(size_t)row * CC + c] = p[c];
        }
    }
}

// ---------------- launch ----------------
extern "C" void kernel_launch(void* const* d_in, const int* in_sizes, int n_in,
                              void* d_out, int out_size)
{
    const float* x     = (const float*)d_in[0];
    const float* W1    = (const float*)d_in[1];
    const float* root1 = (const float*)d_in[2];
    const float* b1    = (const float*)d_in[3];
    const float* W2    = (const float*)d_in[4];
    const float* root2 = (const float*)d_in[5];
    const float* b2    = (const float*)d_in[6];
    const float* Wc    = (const float*)d_in[7];
    const float* bc    = (const float*)d_in[8];
    const void*  ei    = d_in[9];
    const void*  et    = d_in[10];
    float* out = (float*)d_out;

    int n  = in_sizes[0] / HH;     // 50000
    int e  = in_sizes[10];         // 800000
    int n3 = n * RR;

    // single cooperative kernel builds the (dst,rel)-keyed CSR, one atomic pass
    {
        const int* w32 = (const int*)ei;
        void* args[] = { (void*)&w32, (void*)&ei, (void*)&et, (void*)&e, (void*)&n3 };
        cudaLaunchCooperativeKernel((const void*)csr_k,
                                    dim3(CSR_BLOCKS), dim3(CSR_THREADS),
                                    args, 0, 0);
    }

    int aggBlocks  = (n * 32 + 255) / 256;
    int gemmBlocks = (n + 127) / 128;

    // layer 1
    agg_k<<<aggBlocks, 256>>>(x, n, 1);
    rgcn_gemm_k<<<gemmBlocks, 128>>>(x, W1, root1, b1, Wc, bc, out, n, 1);

    // layer 2 (head fused)
    agg_k<<<aggBlocks, 256>>>(x, n, 2);
    rgcn_gemm_k<<<gemmBlocks, 128>>>(x, W2, root2, b2, Wc, bc, out, n, 2);
}

// round 15
// speedup vs baseline: 1.1191x; 1.0124x over previous
#include <cuda_runtime.h>
#include <cooperative_groups.h>
namespace cg = cooperative_groups;

#define NMAX 50000
#define EMAX 800000
#define RR 3
#define HH 64
#define CC 5
#define N3MAX (NMAX * RR)
#define SLICE ((size_t)NMAX * HH)
#define CSR_BLOCKS 148
#define CSR_THREADS 1024

typedef unsigned long long u64;

// ---------------- device scratch (total ~59.1 MiB < 62 MiB proven limit) ----------------
// slices 0..2: per-relation agg means; slice 3: h1
__device__ __align__(16) float g_pool[4 * SLICE];
__device__ int  g_cnt[N3MAX];           // zero at entry (module-load zero / self-cleaned)
__device__ int  g_offs[N3MAX + 1];
__device__ int  g_bsum[CSR_BLOCKS];
__device__ u64  g_krec[EMAX];           // key(18b) | rank(28b) | src(18b)
__device__ int  g_esrc[EMAX];

// ---------------- one cooperative kernel: detect + count&rank + scan + place ----------------
__global__ __launch_bounds__(CSR_THREADS) void csr_k(
    const int* __restrict__ w32,
    const void* __restrict__ ei,
    const void* __restrict__ et,
    int e, int n3)
{
    cg::grid_group grid = cg::this_grid();
    __shared__ int sh[CSR_THREADS];
    __shared__ int blockPrefix;
    __shared__ int nz;

    int tid = threadIdx.x;
    int bid = blockIdx.x;
    int gthreads = gridDim.x * blockDim.x;
    int gi = bid * CSR_THREADS + tid;

    // ---- phase 0: per-block int64/int32 width detection ----
    if (tid == 0) nz = 0;
    __syncthreads();
    {
        int npairs = e < 1024 ? e : 1024;
        int local = 0;
        for (int j = tid; j < npairs; j += CSR_THREADS)
            if (w32[2 * j + 1] != 0) local = 1;
        if (local) atomicExch(&nz, 1);
    }
    __syncthreads();
    const int is64 = (nz == 0);

    const long long* ei64 = (const long long*)ei;
    const int*       ei32 = (const int*)ei;
    const long long* et64 = (const long long*)et;
    const int*       et32 = (const int*)et;

    // ---- phase 1: single edge-decode pass — count + rank + packed record ----
    for (int i = gi; i < e; i += gthreads) {
        int src = is64 ? (int)ei64[i]                : ei32[i];
        int dst = is64 ? (int)ei64[(long long)e + i] : ei32[e + i];
        int r   = is64 ? (int)et64[i]                : et32[i];
        int key = dst * RR + r;
        int rank = atomicAdd(&g_cnt[key], 1);
        g_krec[i] = ((u64)key << 46) | ((u64)rank << 18) | (u64)(unsigned)src;
    }
    grid.sync();

    // ---- phase 2: per-block scan + self-clean g_cnt ----
    int v = (gi < n3) ? g_cnt[gi] : 0;
    if (gi < n3) g_cnt[gi] = 0;             // ready for next graph replay
    sh[tid] = v;
    __syncthreads();
    for (int off = 1; off < CSR_THREADS; off <<= 1) {
        int t = (tid >= off) ? sh[tid - off] : 0;
        __syncthreads();
        sh[tid] += t;
        __syncthreads();
    }
    int incl = sh[tid];
    if (tid == CSR_THREADS - 1) g_bsum[bid] = incl;
    grid.sync();

    // ---- phase 3: prefix of block sums; write offs ----
    if (tid < 32) {
        int run = 0;
        for (int j = tid; j < bid; j += 32) run += g_bsum[j];
        #pragma unroll
        for (int o = 16; o > 0; o >>= 1)
            run += __shfl_down_sync(0xffffffffu, run, o);
        if (tid == 0) blockPrefix = run;
    }
    __syncthreads();
    if (gi < n3) g_offs[gi] = blockPrefix + incl - v;
    if (gi == n3) g_offs[n3] = e;
    grid.sync();

    // ---- phase 4: atomic-free placement from packed records ----
    for (int i = gi; i < e; i += gthreads) {
        u64 rec = g_krec[i];
        int key  = (int)(rec >> 46);
        int rank = (int)((rec >> 18) & 0xFFFFFFFu);
        int src  = (int)(rec & 0x3FFFFu);
        g_esrc[g_offs[key] + rank] = src;
    }
}

// ---------------- node-major aggregation: warp per dst, half-warp float4 rows ----------------
// 16 lanes cover one source row (16 x float4 = 64 floats). Lanes 0-15 take even
// edges, lanes 16-31 odd edges; shfl_xor(16) folds the halves at the end.
__global__ void agg_k(const float* __restrict__ x, int n, int layer) {
    int gt = blockIdx.x * blockDim.x + threadIdx.x;
    int w = gt >> 5;
    int lane = gt & 31;
    if (w >= n) return;

    int half = lane >> 4;       // 0 or 1
    int li   = lane & 15;       // float4 slot within row

    const float4* xin = (const float4*)((layer == 1) ? x : (g_pool + 3 * SLICE));

    int o0 = __ldg(&g_offs[3 * w]);
    int o1 = __ldg(&g_offs[3 * w + 1]);
    int o2 = __ldg(&g_offs[3 * w + 2]);
    int o3 = __ldg(&g_offs[3 * w + 3]);

    #pragma unroll
    for (int r = 0; r < RR; r++) {
        int s = (r == 0) ? o0 : (r == 1) ? o1 : o2;
        int t = (r == 0) ? o1 : (r == 1) ? o2 : o3;

        float4 A = make_float4(0.f, 0.f, 0.f, 0.f);
        float4 B = make_float4(0.f, 0.f, 0.f, 0.f);
        int i = s + half;
        for (; i + 2 < t; i += 4) {
            int s0 = __ldg(&g_esrc[i]);
            int s1 = __ldg(&g_esrc[i + 2]);
            float4 v0 = __ldg(&xin[(size_t)s0 * 16 + li]);
            float4 v1 = __ldg(&xin[(size_t)s1 * 16 + li]);
            A.x += v0.x; A.y += v0.y; A.z += v0.z; A.w += v0.w;
            B.x += v1.x; B.y += v1.y; B.z += v1.z; B.w += v1.w;
        }
        if (i < t) {
            int s0 = __ldg(&g_esrc[i]);
            float4 v0 = __ldg(&xin[(size_t)s0 * 16 + li]);
            A.x += v0.x; A.y += v0.y; A.z += v0.z; A.w += v0.w;
        }
        A.x += B.x; A.y += B.y; A.z += B.z; A.w += B.w;

        // fold odd half into even half
        A.x += __shfl_xor_sync(0xffffffffu, A.x, 16);
        A.y += __shfl_xor_sync(0xffffffffu, A.y, 16);
        A.z += __shfl_xor_sync(0xffffffffu, A.z, 16);
        A.w += __shfl_xor_sync(0xffffffffu, A.w, 16);

        int cnt = t - s;
        float inv = 1.0f / (float)(cnt > 0 ? cnt : 1);
        if (half == 0) {
            float4* o = (float4*)(g_pool + (size_t)r * SLICE + (size_t)w * HH);
            o[li] = make_float4(A.x * inv, A.y * inv, A.z * inv, A.w * inv);
        }
    }
}

// ---------------- packed f32x2 helpers (value semantics only) ----------------
__device__ __forceinline__ u64 pack2(float x) {
    u64 r;
    asm("mov.b64 %0, {%1, %1};" : "=l"(r) : "f"(x));
    return r;
}
__device__ __forceinline__ u64 pack2two(float x, float y) {
    u64 r;
    asm("mov.b64 %0, {%1, %2};" : "=l"(r) : "f"(x), "f"(y));
    return r;
}
__device__ __forceinline__ u64 ffma2(u64 a, u64 b, u64 c) {
    u64 d;
    asm("fma.rn.f32x2 %0, %1, %2, %3;" : "=l"(d) : "l"(a), "l"(b), "l"(c));
    return d;
}
__device__ __forceinline__ float2 unpack2(u64 v) {
    float2 f;
    asm("mov.b64 {%0, %1}, %2;" : "=f"(f.x), "=f"(f.y) : "l"(v));
    return f;
}

// ---------------- fused layer GEMM (+head on layer 2) ----------------
__global__ __launch_bounds__(128) void rgcn_gemm_k(
    const float* __restrict__ x,
    const float* __restrict__ Wrel,
    const float* __restrict__ root,
    const float* __restrict__ bias,
    const float* __restrict__ Wc,
    const float* __restrict__ bc,
    float* __restrict__ outHead,
    int n, int layer)
{
    __shared__ __align__(16) float Ws[HH * HH];
    __shared__ float Wcs[HH * CC];
    __shared__ float bcs[CC];
    int tid = threadIdx.x;
    int row = blockIdx.x * 128 + tid;
    int crow = row < n ? row : 0;

    if (layer == 2) {
        for (int i = tid; i < HH * CC; i += 128) Wcs[i] = Wc[i];
        if (tid < CC) bcs[tid] = bc[tid];
    }

    u64 acc[32];
    {
        const float2* b2 = (const float2*)bias;
        #pragma unroll
        for (int j = 0; j < 32; j++) { float2 b = b2[j]; acc[j] = pack2two(b.x, b.y); }
    }

    const float* xin = (layer == 1) ? x : (g_pool + 3 * SLICE);

    for (int m = 0; m < 4; m++) {
        const float* W = (m == 0) ? root : (Wrel + (size_t)(m - 1) * HH * HH);
        __syncthreads();
        {
            const float4* w4 = (const float4*)W;
            float4* s4 = (float4*)Ws;
            for (int i = tid; i < HH * HH / 4; i += 128) s4[i] = w4[i];
        }
        __syncthreads();

        const float* in = (m == 0) ? xin : (g_pool + (size_t)(m - 1) * SLICE);
        const float4* x4 = (const float4*)(in + (size_t)crow * HH);

        #pragma unroll 4
        for (int k4 = 0; k4 < 16; k4++) {
            float4 v = x4[k4];
            #define GSTEP(E, KK)                                                   \
            {                                                                      \
                u64 p = pack2(E);                                                  \
                const ulonglong2* wr = (const ulonglong2*)&Ws[(4 * k4 + KK) * HH]; \
                _Pragma("unroll")                                                  \
                for (int j = 0; j < 16; j++) {                                     \
                    ulonglong2 w2 = wr[j];                                         \
                    acc[2 * j]     = ffma2(p, w2.x, acc[2 * j]);                   \
                    acc[2 * j + 1] = ffma2(p, w2.y, acc[2 * j + 1]);               \
                }                                                                  \
            }
            GSTEP(v.x, 0)
            GSTEP(v.y, 1)
            GSTEP(v.z, 2)
            GSTEP(v.w, 3)
            #undef GSTEP
        }
    }

    if (layer == 1) {
        if (row < n) {
            float4* o4 = (float4*)(g_pool + 3 * SLICE + (size_t)row * HH);
            #pragma unroll
            for (int j = 0; j < 16; j++) {
                float2 lo = unpack2(acc[2 * j]);
                float2 hi = unpack2(acc[2 * j + 1]);
                float a = lo.x > 0.f ? lo.x : 0.f;
                float b = lo.y > 0.f ? lo.y : 0.f;
                float c = hi.x > 0.f ? hi.x : 0.f;
                float d = hi.y > 0.f ? hi.y : 0.f;
                o4[j] = make_float4(a, b, c, d);
            }
        }
    } else {
        float p[CC];
        #pragma unroll
        for (int c = 0; c < CC; c++) p[c] = bcs[c];
        #pragma unroll
        for (int j = 0; j < 32; j++) {
            float2 v = unpack2(acc[j]);
            float h0 = v.x > 0.f ? v.x : 0.f;
            float h1 = v.y > 0.f ? v.y : 0.f;
            int k0 = 2 * j;
            #pragma unroll
            for (int c = 0; c < CC; c++)
                p[c] += h0 * Wcs[k0 * CC + c] + h1 * Wcs[(k0 + 1) * CC + c];
        }
        if (row < n) {
            #pragma unroll
            for (int c = 0; c < CC; c++)
                outHead[(size_t)row * CC + c] = p[c];
        }
    }
}

// ---------------- launch ----------------
extern "C" void kernel_launch(void* const* d_in, const int* in_sizes, int n_in,
                              void* d_out, int out_size)
{
    const float* x     = (const float*)d_in[0];
    const float* W1    = (const float*)d_in[1];
    const float* root1 = (const float*)d_in[2];
    const float* b1    = (const float*)d_in[3];
    const float* W2    = (const float*)d_in[4];
    const float* root2 = (const float*)d_in[5];
    const float* b2    = (const float*)d_in[6];
    const float* Wc    = (const float*)d_in[7];
    const float* bc    = (const float*)d_in[8];
    const void*  ei    = d_in[9];
    const void*  et    = d_in[10];
    float* out = (float*)d_out;

    int n  = in_sizes[0] / HH;     // 50000
    int e  = in_sizes[10];         // 800000
    int n3 = n * RR;

    // single cooperative kernel builds the (dst,rel)-keyed CSR, one atomic pass
    {
        const int* w32 = (const int*)ei;
        void* args[] = { (void*)&w32, (void*)&ei, (void*)&et, (void*)&e, (void*)&n3 };
        cudaLaunchCooperativeKernel((const void*)csr_k,
                                    dim3(CSR_BLOCKS), dim3(CSR_THREADS),
                                    args, 0, 0);
    }

    int aggBlocks  = (n * 32 + 255) / 256;
    int gemmBlocks = (n + 127) / 128;

    // layer 1
    agg_k<<<aggBlocks, 256>>>(x, n, 1);
    rgcn_gemm_k<<<gemmBlocks, 128>>>(x, W1, root1, b1, Wc, bc, out, n, 1);

    // layer 2 (head fused)
    agg_k<<<aggBlocks, 256>>>(x, n, 2);
    rgcn_gemm_k<<<gemmBlocks, 128>>>(x, W2, root2, b2, Wc, bc, out, n, 2);
}

// round 16
// speedup vs baseline: 1.1364x; 1.0154x over previous
#include <cuda_runtime.h>
#include <cooperative_groups.h>
namespace cg = cooperative_groups;

#define NMAX 50000
#define EMAX 800000
#define RR 3
#define HH 64
#define CC 5
#define N3MAX (NMAX * RR)
#define SLICE ((size_t)NMAX * HH)
#define CSR_BLOCKS 148
#define CSR_THREADS 1024

typedef unsigned long long u64;

// ---------------- device scratch (total ~59.1 MiB < 62 MiB proven limit) ----------------
// slices 0..2: per-relation agg means; slice 3: h1
__device__ __align__(16) float g_pool[4 * SLICE];
__device__ int  g_cnt[N3MAX];           // zero at entry (module-load zero / self-cleaned)
__device__ int  g_offs[N3MAX + 1];
__device__ int  g_bsum[CSR_BLOCKS];
__device__ u64  g_krec[EMAX];           // key(18b) | rank(28b) | src(18b)
__device__ int  g_esrc[EMAX];

// ---------------- one cooperative kernel: detect + count&rank + scan + place ----------------
__global__ __launch_bounds__(CSR_THREADS) void csr_k(
    const int* __restrict__ w32,
    const void* __restrict__ ei,
    const void* __restrict__ et,
    int e, int n3)
{
    cg::grid_group grid = cg::this_grid();
    __shared__ int sh[CSR_THREADS];
    __shared__ int blockPrefix;
    __shared__ int nz;

    int tid = threadIdx.x;
    int bid = blockIdx.x;
    int gthreads = gridDim.x * blockDim.x;
    int gi = bid * CSR_THREADS + tid;

    // ---- phase 0: per-block int64/int32 width detection ----
    if (tid == 0) nz = 0;
    __syncthreads();
    {
        int npairs = e < 1024 ? e : 1024;
        int local = 0;
        for (int j = tid; j < npairs; j += CSR_THREADS)
            if (w32[2 * j + 1] != 0) local = 1;
        if (local) atomicExch(&nz, 1);
    }
    __syncthreads();
    const int is64 = (nz == 0);

    const long long* ei64 = (const long long*)ei;
    const int*       ei32 = (const int*)ei;
    const long long* et64 = (const long long*)et;
    const int*       et32 = (const int*)et;

    // ---- phase 1: single edge-decode pass — count + rank + packed record ----
    for (int i = gi; i < e; i += gthreads) {
        int src = is64 ? (int)ei64[i]                : ei32[i];
        int dst = is64 ? (int)ei64[(long long)e + i] : ei32[e + i];
        int r   = is64 ? (int)et64[i]                : et32[i];
        int key = dst * RR + r;
        int rank = atomicAdd(&g_cnt[key], 1);
        g_krec[i] = ((u64)key << 46) | ((u64)rank << 18) | (u64)(unsigned)src;
    }
    grid.sync();

    // ---- phase 2: per-block scan + self-clean g_cnt ----
    int v = (gi < n3) ? g_cnt[gi] : 0;
    if (gi < n3) g_cnt[gi] = 0;             // ready for next graph replay
    sh[tid] = v;
    __syncthreads();
    for (int off = 1; off < CSR_THREADS; off <<= 1) {
        int t = (tid >= off) ? sh[tid - off] : 0;
        __syncthreads();
        sh[tid] += t;
        __syncthreads();
    }
    int incl = sh[tid];
    if (tid == CSR_THREADS - 1) g_bsum[bid] = incl;
    grid.sync();

    // ---- phase 3: prefix of block sums; write offs ----
    if (tid < 32) {
        int run = 0;
        for (int j = tid; j < bid; j += 32) run += g_bsum[j];
        #pragma unroll
        for (int o = 16; o > 0; o >>= 1)
            run += __shfl_down_sync(0xffffffffu, run, o);
        if (tid == 0) blockPrefix = run;
    }
    __syncthreads();
    if (gi < n3) g_offs[gi] = blockPrefix + incl - v;
    if (gi == n3) g_offs[n3] = e;
    grid.sync();

    // ---- phase 4: atomic-free placement from packed records ----
    for (int i = gi; i < e; i += gthreads) {
        u64 rec = g_krec[i];
        int key  = (int)(rec >> 46);
        int rank = (int)((rec >> 18) & 0xFFFFFFFu);
        int src  = (int)(rec & 0x3FFFFu);
        g_esrc[g_offs[key] + rank] = src;
    }
}

// ---------------- node-major aggregation: warp per dst, half-warp float4 rows ----------------
__global__ void agg_k(const float* __restrict__ x, int n, int layer) {
    int gt = blockIdx.x * blockDim.x + threadIdx.x;
    int w = gt >> 5;
    int lane = gt & 31;
    if (w >= n) return;

    int half = lane >> 4;       // 0 or 1
    int li   = lane & 15;       // float4 slot within row

    const float4* xin = (const float4*)((layer == 1) ? x : (g_pool + 3 * SLICE));

    int o0 = __ldg(&g_offs[3 * w]);
    int o1 = __ldg(&g_offs[3 * w + 1]);
    int o2 = __ldg(&g_offs[3 * w + 2]);
    int o3 = __ldg(&g_offs[3 * w + 3]);

    #pragma unroll
    for (int r = 0; r < RR; r++) {
        int s = (r == 0) ? o0 : (r == 1) ? o1 : o2;
        int t = (r == 0) ? o1 : (r == 1) ? o2 : o3;

        float4 A = make_float4(0.f, 0.f, 0.f, 0.f);
        float4 B = make_float4(0.f, 0.f, 0.f, 0.f);
        int i = s + half;
        for (; i + 2 < t; i += 4) {
            int s0 = __ldg(&g_esrc[i]);
            int s1 = __ldg(&g_esrc[i + 2]);
            float4 v0 = __ldg(&xin[(size_t)s0 * 16 + li]);
            float4 v1 = __ldg(&xin[(size_t)s1 * 16 + li]);
            A.x += v0.x; A.y += v0.y; A.z += v0.z; A.w += v0.w;
            B.x += v1.x; B.y += v1.y; B.z += v1.z; B.w += v1.w;
        }
        if (i < t) {
            int s0 = __ldg(&g_esrc[i]);
            float4 v0 = __ldg(&xin[(size_t)s0 * 16 + li]);
            A.x += v0.x; A.y += v0.y; A.z += v0.z; A.w += v0.w;
        }
        A.x += B.x; A.y += B.y; A.z += B.z; A.w += B.w;

        A.x += __shfl_xor_sync(0xffffffffu, A.x, 16);
        A.y += __shfl_xor_sync(0xffffffffu, A.y, 16);
        A.z += __shfl_xor_sync(0xffffffffu, A.z, 16);
        A.w += __shfl_xor_sync(0xffffffffu, A.w, 16);

        int cnt = t - s;
        float inv = 1.0f / (float)(cnt > 0 ? cnt : 1);
        if (half == 0) {
            float4* o = (float4*)(g_pool + (size_t)r * SLICE + (size_t)w * HH);
            o[li] = make_float4(A.x * inv, A.y * inv, A.z * inv, A.w * inv);
        }
    }
}

// ---------------- packed f32x2 helpers (value semantics only) ----------------
__device__ __forceinline__ u64 pack2(float x) {
    u64 r;
    asm("mov.b64 %0, {%1, %1};" : "=l"(r) : "f"(x));
    return r;
}
__device__ __forceinline__ u64 pack2two(float x, float y) {
    u64 r;
    asm("mov.b64 %0, {%1, %2};" : "=l"(r) : "f"(x), "f"(y));
    return r;
}
__device__ __forceinline__ u64 ffma2(u64 a, u64 b, u64 c) {
    u64 d;
    asm("fma.rn.f32x2 %0, %1, %2, %3;" : "=l"(d) : "l"(a), "l"(b), "l"(c));
    return d;
}
__device__ __forceinline__ float2 unpack2(u64 v) {
    float2 f;
    asm("mov.b64 {%0, %1}, %2;" : "=f"(f.x), "=f"(f.y) : "l"(v));
    return f;
}

// ---------------- fused layer GEMM (+head on layer 2), 2-row x 32-col blocking ----------------
// 128 threads/block covering 128 rows: tid = rowpair*2 + colhalf.
// Each thread: rows (base+2*rp, base+2*rp+1), cols [cg*32, cg*32+32).
// LDS per k-step halves vs 1-row tiling (weight fragment feeds two rows).
__global__ __launch_bounds__(128) void rgcn_gemm_k(
    const float* __restrict__ x,
    const float* __restrict__ Wrel,
    const float* __restrict__ root,
    const float* __restrict__ bias,
    const float* __restrict__ Wc,
    const float* __restrict__ bc,
    float* __restrict__ outHead,
    int n, int layer)
{
    __shared__ __align__(16) float Ws[HH * HH];
    __shared__ float Wcs[HH * CC];
    __shared__ float bcs[CC];
    int tid = threadIdx.x;
    int rp = tid >> 1;          // 0..63
    int cg = tid & 1;           // column half
    int r0 = blockIdx.x * 128 + rp * 2;
    int r1 = r0 + 1;
    int c0 = r0 < n ? r0 : 0;
    int c1 = r1 < n ? r1 : 0;

    if (layer == 2) {
        for (int i = tid; i < HH * CC; i += 128) Wcs[i] = Wc[i];
        if (tid < CC) bcs[tid] = bc[tid];
    }

    u64 acc0[16], acc1[16];
    {
        const float2* b2 = (const float2*)(bias + cg * 32);
        #pragma unroll
        for (int j = 0; j < 16; j++) {
            float2 b = b2[j];
            u64 bb = pack2two(b.x, b.y);
            acc0[j] = bb; acc1[j] = bb;
        }
    }

    const float* xin = (layer == 1) ? x : (g_pool + 3 * SLICE);

    for (int m = 0; m < 4; m++) {
        const float* W = (m == 0) ? root : (Wrel + (size_t)(m - 1) * HH * HH);
        __syncthreads();
        {
            const float4* w4 = (const float4*)W;
            float4* s4 = (float4*)Ws;
            for (int i = tid; i < HH * HH / 4; i += 128) s4[i] = w4[i];
        }
        __syncthreads();

        const float* in = (m == 0) ? xin : (g_pool + (size_t)(m - 1) * SLICE);
        const float4* x40 = (const float4*)(in + (size_t)c0 * HH);
        const float4* x41 = (const float4*)(in + (size_t)c1 * HH);

        #pragma unroll 4
        for (int k4 = 0; k4 < 16; k4++) {
            float4 v0 = x40[k4];
            float4 v1 = x41[k4];
            #define GSTEP(E0, E1, KK)                                                        \
            {                                                                                \
                u64 p0 = pack2(E0);                                                          \
                u64 p1 = pack2(E1);                                                          \
                const ulonglong2* wr = (const ulonglong2*)&Ws[(4 * k4 + KK) * HH + cg * 32]; \
                _Pragma("unroll")                                                            \
                for (int j = 0; j < 8; j++) {                                                \
                    ulonglong2 w2 = wr[j];                                                   \
                    acc0[2 * j]     = ffma2(p0, w2.x, acc0[2 * j]);                          \
                    acc0[2 * j + 1] = ffma2(p0, w2.y, acc0[2 * j + 1]);                      \
                    acc1[2 * j]     = ffma2(p1, w2.x, acc1[2 * j]);                          \
                    acc1[2 * j + 1] = ffma2(p1, w2.y, acc1[2 * j + 1]);                      \
                }                                                                            \
            }
            GSTEP(v0.x, v1.x, 0)
            GSTEP(v0.y, v1.y, 1)
            GSTEP(v0.z, v1.z, 2)
            GSTEP(v0.w, v1.w, 3)
            #undef GSTEP
        }
    }

    if (layer == 1) {
        float* h1 = g_pool + 3 * SLICE;
        if (r0 < n) {
            float4* o4 = (float4*)(h1 + (size_t)r0 * HH + cg * 32);
            #pragma unroll
            for (int j = 0; j < 8; j++) {
                float2 lo = unpack2(acc0[2 * j]);
                float2 hi = unpack2(acc0[2 * j + 1]);
                o4[j] = make_float4(lo.x > 0.f ? lo.x : 0.f, lo.y > 0.f ? lo.y : 0.f,
                                    hi.x > 0.f ? hi.x : 0.f, hi.y > 0.f ? hi.y : 0.f);
            }
        }
        if (r1 < n) {
            float4* o4 = (float4*)(h1 + (size_t)r1 * HH + cg * 32);
            #pragma unroll
            for (int j = 0; j < 8; j++) {
                float2 lo = unpack2(acc1[2 * j]);
                float2 hi = unpack2(acc1[2 * j + 1]);
                o4[j] = make_float4(lo.x > 0.f ? lo.x : 0.f, lo.y > 0.f ? lo.y : 0.f,
                                    hi.x > 0.f ? hi.x : 0.f, hi.y > 0.f ? hi.y : 0.f);
            }
        }
    } else {
        // fused head: partial logits over this thread's 32 h2 columns, for both rows
        float p0[CC], p1[CC];
        #pragma unroll
        for (int c = 0; c < CC; c++) { p0[c] = 0.f; p1[c] = 0.f; }
        #pragma unroll
        for (int j = 0; j < 16; j++) {
            float2 v0 = unpack2(acc0[j]);
            float2 v1 = unpack2(acc1[j]);
            float a0 = v0.x > 0.f ? v0.x : 0.f;
            float a1 = v0.y > 0.f ? v0.y : 0.f;
            float b0 = v1.x > 0.f ? v1.x : 0.f;
            float b1 = v1.y > 0.f ? v1.y : 0.f;
            int k0 = cg * 32 + 2 * j;
            #pragma unroll
            for (int c = 0; c < CC; c++) {
                float wA = Wcs[k0 * CC + c];
                float wB = Wcs[(k0 + 1) * CC + c];
                p0[c] += a0 * wA + a1 * wB;
                p1[c] += b0 * wA + b1 * wB;
            }
        }
        // combine the cg pair (adjacent lanes)
        #pragma unroll
        for (int c = 0; c < CC; c++) {
            p0[c] += __shfl_xor_sync(0xffffffffu, p0[c], 1);
            p1[c] += __shfl_xor_sync(0xffffffffu, p1[c], 1);
        }
        if (cg == 0) {
            if (r0 < n) {
                #pragma unroll
                for (int c = 0; c < CC; c++)
                    outHead[(size_t)r0 * CC + c] = p0[c] + bcs[c];
            }
            if (r1 < n) {
                #pragma unroll
                for (int c = 0; c < CC; c++)
                    outHead[(size_t)r1 * CC + c] = p1[c] + bcs[c];
            }
        }
    }
}

// ---------------- launch ----------------
extern "C" void kernel_launch(void* const* d_in, const int* in_sizes, int n_in,
                              void* d_out, int out_size)
{
    const float* x     = (const float*)d_in[0];
    const float* W1    = (const float*)d_in[1];
    const float* root1 = (const float*)d_in[2];
    const float* b1    = (const float*)d_in[3];
    const float* W2    = (const float*)d_in[4];
    const float* root2 = (const float*)d_in[5];
    const float* b2    = (const float*)d_in[6];
    const float* Wc    = (const float*)d_in[7];
    const float* bc    = (const float*)d_in[8];
    const void*  ei    = d_in[9];
    const void*  et    = d_in[10];
    float* out = (float*)d_out;

    int n  = in_sizes[0] / HH;     // 50000
    int e  = in_sizes[10];         // 800000
    int n3 = n * RR;

    // single cooperative kernel builds the (dst,rel)-keyed CSR, one atomic pass
    {
        const int* w32 = (const int*)ei;
        void* args[] = { (void*)&w32, (void*)&ei, (void*)&et, (void*)&e, (void*)&n3 };
        cudaLaunchCooperativeKernel((const void*)csr_k,
                                    dim3(CSR_BLOCKS), dim3(CSR_THREADS),
                                    args, 0, 0);
    }

    int aggBlocks  = (n * 32 + 255) / 256;
    int gemmBlocks = (n + 127) / 128;

    // layer 1
    agg_k<<<aggBlocks, 256>>>(x, n, 1);
    rgcn_gemm_k<<<gemmBlocks, 128>>>(x, W1, root1, b1, Wc, bc, out, n, 1);

    // layer 2 (head fused)
    agg_k<<<aggBlocks, 256>>>(x, n, 2);
    rgcn_gemm_k<<<gemmBlocks, 128>>>(x, W2, root2, b2, Wc, bc, out, n, 2);
}